// round 16
// baseline (speedup 1.0000x reference)
#include <cuda_runtime.h>
#include <cstdint>

#define SEQ   2048
#define BATCH 32
#define IDIM  256
#define HDIM  256
#define G4    1024

__device__ float g_xg[SEQ * BATCH * G4];

__device__ __forceinline__ void ffma2(uint64_t& acc, uint64_t a, uint64_t b) {
    asm("fma.rn.f32x2 %0, %1, %2, %0;" : "+l"(acc) : "l"(a), "l"(b));
}
__device__ __forceinline__ float hsum2(uint64_t a) {
    uint32_t lo, hi;
    asm("mov.b64 {%0,%1}, %2;" : "=r"(lo), "=r"(hi) : "l"(a));
    return __uint_as_float(lo) + __uint_as_float(hi);
}

// ---------------------------------------------------------------------------
// Kernel 1 (unchanged control): Xg = x @ W_ih^T + b_ih + b_hh
// ---------------------------------------------------------------------------
#define BM 64
#define BN 64
#define BK 32

__global__ __launch_bounds__(256) void xproj_kernel(
    const float* __restrict__ x,
    const float* __restrict__ Wih,
    const float* __restrict__ bih,
    const float* __restrict__ bhh)
{
    __shared__ float As[BK][BM];
    __shared__ float Bs[BK][BN];

    const int tid  = threadIdx.x;
    const int mblk = blockIdx.x;
    const int nblk = blockIdx.y;

    const float* Arow = x   + (size_t)mblk * BM * IDIM;
    const float* Brow = Wih + (size_t)nblk * BN * IDIM;

    const int tx = tid & 15;
    const int ty = tid >> 4;

    uint64_t acc01[4] = {}, acc23[4] = {};

    const int lr  = tid >> 2;
    const int lkq = (tid & 3) * 8;

    for (int k0 = 0; k0 < IDIM; k0 += BK) {
        {
            float4 v0 = *(const float4*)(Arow + lr * IDIM + k0 + lkq);
            float4 v1 = *(const float4*)(Arow + lr * IDIM + k0 + lkq + 4);
            As[lkq + 0][lr] = v0.x; As[lkq + 1][lr] = v0.y;
            As[lkq + 2][lr] = v0.z; As[lkq + 3][lr] = v0.w;
            As[lkq + 4][lr] = v1.x; As[lkq + 5][lr] = v1.y;
            As[lkq + 6][lr] = v1.z; As[lkq + 7][lr] = v1.w;

            float4 w0 = *(const float4*)(Brow + lr * IDIM + k0 + lkq);
            float4 w1 = *(const float4*)(Brow + lr * IDIM + k0 + lkq + 4);
            Bs[lkq + 0][lr] = w0.x; Bs[lkq + 1][lr] = w0.y;
            Bs[lkq + 2][lr] = w0.z; Bs[lkq + 3][lr] = w0.w;
            Bs[lkq + 4][lr] = w1.x; Bs[lkq + 5][lr] = w1.y;
            Bs[lkq + 6][lr] = w1.z; Bs[lkq + 7][lr] = w1.w;
        }
        __syncthreads();

        #pragma unroll
        for (int kk = 0; kk < BK; kk++) {
            float4 av = *(const float4*)&As[kk][ty * 4];
            const uint64_t b01 = *(const uint64_t*)&Bs[kk][tx * 4];
            const uint64_t b23 = *(const uint64_t*)&Bs[kk][tx * 4 + 2];
            float a[4] = {av.x, av.y, av.z, av.w};
            #pragma unroll
            for (int i = 0; i < 4; i++) {
                uint64_t aa;
                asm("mov.b64 %0, {%1,%1};" : "=l"(aa) : "f"(a[i]));
                ffma2(acc01[i], aa, b01);
                ffma2(acc23[i], aa, b23);
            }
        }
        __syncthreads();
    }

    const int mb = mblk * BM + ty * 4;
    const int nb = nblk * BN + tx * 4;
    float bias[4];
    #pragma unroll
    for (int jj = 0; jj < 4; jj++)
        bias[jj] = bih[nb + jj] + bhh[nb + jj];

    #pragma unroll
    for (int i = 0; i < 4; i++) {
        uint32_t lo, hi, lo2, hi2;
        asm("mov.b64 {%0,%1}, %2;" : "=r"(lo), "=r"(hi) : "l"(acc01[i]));
        asm("mov.b64 {%0,%1}, %2;" : "=r"(lo2), "=r"(hi2) : "l"(acc23[i]));
        float4 v;
        v.x = __uint_as_float(lo)  + bias[0];
        v.y = __uint_as_float(hi)  + bias[1];
        v.z = __uint_as_float(lo2) + bias[2];
        v.w = __uint_as_float(hi2) + bias[3];
        *(float4*)&g_xg[(size_t)(mb + i) * G4 + nb] = v;
    }
}

// ---------------------------------------------------------------------------
// Kernel 2: dual-chain recurrence on DISJOINT warp groups, 16-CTA clusters.
// 8 clusters x 16 CTAs (128 SMs); cluster owns 4 batches = 2 chains of 2.
// CTA rank owns 16 hidden units (64 gate rows). 576 threads:
//   warps 0-7  : chain A compute (g = w&7: kseg = g>>1, lr = (g&1)*32+lane)
//   warps 8-15 : chain B compute
//   warp 16/17 : owner A / owner B (lane: bb = lane>>4, u = lane&15)
// Each chain runs its own independent 2048-step loop; the HW scheduler
// overlaps A's sync/hop latency with B's k-loop. Barriers: bar 1/2 x 288.
// ---------------------------------------------------------------------------
__device__ __forceinline__ void mbar_wait(uint32_t addr, unsigned par) {
    asm volatile(
        "{\n\t"
        ".reg .pred P;\n\t"
        "WAIT_%=:\n\t"
        "mbarrier.try_wait.parity.acquire.cta.shared::cta.b64 P, [%0], %1, 0x989680;\n\t"
        "@P bra DONE_%=;\n\t"
        "bra WAIT_%=;\n\t"
        "DONE_%=:\n\t"
        "}"
        :: "r"(addr), "r"(par) : "memory");
}

#define TX_PER_BUF 2048   // 16 ranks x 16 units x 2 bb x 4 B

__global__ void __launch_bounds__(576, 1)
lstm_rec_kernel(const float* __restrict__ Whh,
                const float* __restrict__ h0,
                const float* __restrict__ c0,
                float* __restrict__ out)
{
    __shared__ float h_s[2][2][2][HDIM];      // [chain][buf][bb][k]
    __shared__ float red_s[2][2][4][2][64];   // [chain][rd][kseg][bb][lr]
    __shared__ alignas(8) unsigned long long mbar[4];  // [chain*2 + buf]

    const int tid  = threadIdx.x;
    const int lane = tid & 31;
    const int w    = tid >> 5;

    unsigned rank;
    asm("mov.u32 %0, %%cluster_ctarank;" : "=r"(rank));
    const int b0 = (blockIdx.x >> 4) * 4;

    const uint32_t h_base  = (uint32_t)__cvta_generic_to_shared(&h_s[0][0][0][0]);
    const uint32_t mb_addr = (uint32_t)__cvta_generic_to_shared(&mbar[0]);

    for (int i = tid; i < 4 * HDIM; i += 576) {
        const int bb = i >> 8, k = i & 255;
        h_s[bb >> 1][0][bb & 1][k] = h0[(size_t)(b0 + bb) * HDIM + k];
    }
    if (tid == 0) {
        #pragma unroll
        for (int q = 0; q < 4; q++) {
            asm volatile("mbarrier.init.shared.b64 [%0], %1;" :: "r"(mb_addr + q * 8), "r"(1) : "memory");
            asm volatile("mbarrier.arrive.expect_tx.shared.b64 _, [%0], %1;"
                         :: "r"(mb_addr + q * 8), "r"(TX_PER_BUF) : "memory");
        }
    }
    __syncthreads();
    asm volatile("barrier.cluster.arrive.aligned;" ::: "memory");
    asm volatile("barrier.cluster.wait.aligned;" ::: "memory");

    if (w < 16) {
        // =================== COMPUTE WARPS (one chain each) ===================
        const int P    = w >> 3;                   // chain
        const int g    = w & 7;
        const int kseg = g >> 1;
        const int lr   = (g & 1) * 32 + lane;      // 0..63 local gate row
        const int R    = (lr >> 4) * 256 + (int)rank * 16 + (lr & 15);
        const bool rearm = (g == 0) && (lane == 0);

        uint64_t wp[32];
        {
            const float* W = Whh + (size_t)R * HDIM + kseg * 64;
            #pragma unroll
            for (int i = 0; i < 16; i++) {
                float4 v = *(const float4*)(W + 4 * i);
                asm("mov.b64 %0, {%1,%2};" : "=l"(wp[2*i+0]) : "f"(v.x), "f"(v.y));
                asm("mov.b64 %0, {%1,%2};" : "=l"(wp[2*i+1]) : "f"(v.z), "f"(v.w));
            }
        }

        auto kphase = [&](int rd, bool dowait, unsigned par) {
            const uint32_t mb_rd = mb_addr + (uint32_t)(P * 2 + rd) * 8;
            if (dowait) {
                mbar_wait(mb_rd, par);
                if (rearm)
                    asm volatile("mbarrier.arrive.expect_tx.shared.b64 _, [%0], %1;"
                                 :: "r"(mb_rd), "r"(TX_PER_BUF) : "memory");
            }
            const uint32_t a0 = h_base + (uint32_t)((P * 2 + rd) * 2 * 256 + kseg * 64) * 4;
            const uint32_t a1 = a0 + 1024;
            uint64_t acc0 = 0ull, acc1 = 0ull;
            #pragma unroll
            for (int i = 0; i < 64; i += 4) {
                uint64_t u01, u23, v01, v23;
                asm volatile("ld.shared.v2.u64 {%0,%1}, [%2];"
                             : "=l"(u01), "=l"(u23) : "r"(a0 + i * 4));
                asm volatile("ld.shared.v2.u64 {%0,%1}, [%2];"
                             : "=l"(v01), "=l"(v23) : "r"(a1 + i * 4));
                ffma2(acc0, wp[i / 2 + 0], u01);
                ffma2(acc1, wp[i / 2 + 0], v01);
                ffma2(acc0, wp[i / 2 + 1], u23);
                ffma2(acc1, wp[i / 2 + 1], v23);
            }
            red_s[P][rd][kseg][0][lr] = hsum2(acc0);
            red_s[P][rd][kseg][1][lr] = hsum2(acc1);
            if (P == 0)
                asm volatile("bar.arrive 1, 288;" ::: "memory");
            else
                asm volatile("bar.arrive 2, 288;" ::: "memory");
        };

        unsigned par[2] = {0, 0};
        kphase(0, false, 0);                             // t = SEQ-1, rd=0
        for (int t = SEQ - 2; t >= 1; t--) {
            const int rd = (t + 1) & 1;
            kphase(rd, true, par[rd]);
            par[rd] ^= 1;
        }
        kphase(1, true, par[1]);                         // t = 0, rd=1
    } else {
        // =================== OWNER WARPS (one chain each) ===================
        const int P = w - 16;
        const int bb = lane >> 4;
        const int u  = lane & 15;
        const int kglob = (int)rank * 16 + u;
        const int bcur = b0 + 2 * P + bb;
        const uint32_t mb_delta = mb_addr - h_base;

        uint32_t ph[16];
        #pragma unroll
        for (int r = 0; r < 16; r++)
            asm("mapa.shared::cluster.u32 %0, %1, %2;" : "=r"(ph[r]) : "r"(h_base), "r"(r));

        float c_reg = c0[(size_t)bcur * HDIM + kglob];
        float h_keep = 0.f;

        for (int t = SEQ - 1; t >= 0; t--) {
            const int rd = (t + 1) & 1;

            // xg prefetch (covered by the bar wait)
            const float* xp = g_xg + ((size_t)t * BATCH + bcur) * G4 + kglob;
            const float a0v = __ldg(xp);
            const float a1v = __ldg(xp + 256);
            const float a2v = __ldg(xp + 512);
            const float a3v = __ldg(xp + 768);

            if (P == 0)
                asm volatile("bar.sync 1, 288;" ::: "memory");
            else
                asm volatile("bar.sync 2, 288;" ::: "memory");

            float s0 = a0v, s1 = a1v, s2 = a2v, s3 = a3v;
            #pragma unroll
            for (int ks = 0; ks < 4; ks++) {
                const float* rp = &red_s[P][rd][ks][bb][0];
                s0 += rp[ 0 + u];
                s1 += rp[16 + u];
                s2 += rp[32 + u];
                s3 += rp[48 + u];
            }

            const float ig = __fdividef(1.f, 1.f + __expf(-s0));
            const float fg = __fdividef(1.f, 1.f + __expf(-s1));
            const float gt = 1.f - 2.f * __fdividef(1.f, 1.f + __expf(2.f * s2));
            const float og = __fdividef(1.f, 1.f + __expf(-s3));

            c_reg = fg * c_reg + ig * gt;
            const float h = og * (1.f - 2.f * __fdividef(1.f, 1.f + __expf(2.f * c_reg)));
            h_keep = h;

            if (t > 0) {
                const int wr = rd ^ 1;
                const float hn = __shfl_down_sync(0xffffffffu, h, 1);
                if ((u & 1) == 0) {
                    uint64_t hp;
                    asm("mov.b64 %0, {%1,%2};" : "=l"(hp) : "f"(h), "f"(hn));
                    const uint32_t ho = (uint32_t)((((P * 2 + wr) * 2 + bb) * 256 + kglob) * 4);
                    const uint32_t mo = mb_delta + (uint32_t)(P * 2 + wr) * 8;
                    #pragma unroll
                    for (int r = 0; r < 16; r++) {
                        asm volatile(
                            "st.async.shared::cluster.mbarrier::complete_tx::bytes.b64 [%0], %1, [%2];"
                            :: "r"(ph[r] + ho), "l"(hp), "r"(ph[r] + mo) : "memory");
                    }
                }
            }

            out[((size_t)t * BATCH + bcur) * HDIM + kglob] = h;
        }

        float* hT = out + (size_t)SEQ * BATCH * HDIM;
        float* cT = hT + (size_t)BATCH * HDIM;
        hT[(size_t)bcur * HDIM + kglob] = h_keep;
        cT[(size_t)bcur * HDIM + kglob] = c_reg;
    }
}

// ---------------------------------------------------------------------------
extern "C" void kernel_launch(void* const* d_in, const int* in_sizes, int n_in,
                              void* d_out, int out_size)
{
    (void)in_sizes; (void)n_in; (void)out_size;
    const float* x   = (const float*)d_in[0];
    const float* h0  = (const float*)d_in[1];
    const float* c0  = (const float*)d_in[2];
    const float* Wih = (const float*)d_in[3];
    const float* Whh = (const float*)d_in[4];
    const float* bih = (const float*)d_in[5];
    const float* bhh = (const float*)d_in[6];
    float* out = (float*)d_out;

    dim3 gridP(65536 / BM, G4 / BN);   // (1024, 16)
    xproj_kernel<<<gridP, 256>>>(x, Wih, bih, bhh);

    static bool attr_done = false;
    if (!attr_done) {
        cudaFuncSetAttribute(lstm_rec_kernel,
                             cudaFuncAttributeNonPortableClusterSizeAllowed, 1);
        attr_done = true;
    }

    cudaLaunchConfig_t cfg = {};
    cfg.gridDim  = dim3(128, 1, 1);    // 8 clusters x 16 CTAs
    cfg.blockDim = dim3(576, 1, 1);
    cudaLaunchAttribute attrs[1];
    attrs[0].id = cudaLaunchAttributeClusterDimension;
    attrs[0].val.clusterDim.x = 16;
    attrs[0].val.clusterDim.y = 1;
    attrs[0].val.clusterDim.z = 1;
    cfg.attrs = attrs;
    cfg.numAttrs = 1;
    cudaLaunchKernelEx(&cfg, lstm_rec_kernel, Whh, h0, c0, out);
}

// round 17
// speedup vs baseline: 1.3863x; 1.3863x over previous
#include <cuda_runtime.h>
#include <cstdint>

#define SEQ   2048
#define BATCH 32
#define IDIM  256
#define HDIM  256
#define G4    1024

__device__ float g_xg[SEQ * BATCH * G4];

__device__ __forceinline__ void ffma2(uint64_t& acc, uint64_t a, uint64_t b) {
    asm("fma.rn.f32x2 %0, %1, %2, %0;" : "+l"(acc) : "l"(a), "l"(b));
}
__device__ __forceinline__ float hsum2(uint64_t a) {
    uint32_t lo, hi;
    asm("mov.b64 {%0,%1}, %2;" : "=r"(lo), "=r"(hi) : "l"(a));
    return __uint_as_float(lo) + __uint_as_float(hi);
}

// ---------------------------------------------------------------------------
// Kernel 1 (unchanged control): Xg = x @ W_ih^T + b_ih + b_hh
// ---------------------------------------------------------------------------
#define BM 64
#define BN 64
#define BK 32

__global__ __launch_bounds__(256) void xproj_kernel(
    const float* __restrict__ x,
    const float* __restrict__ Wih,
    const float* __restrict__ bih,
    const float* __restrict__ bhh)
{
    __shared__ float As[BK][BM];
    __shared__ float Bs[BK][BN];

    const int tid  = threadIdx.x;
    const int mblk = blockIdx.x;
    const int nblk = blockIdx.y;

    const float* Arow = x   + (size_t)mblk * BM * IDIM;
    const float* Brow = Wih + (size_t)nblk * BN * IDIM;

    const int tx = tid & 15;
    const int ty = tid >> 4;

    uint64_t acc01[4] = {}, acc23[4] = {};

    const int lr  = tid >> 2;
    const int lkq = (tid & 3) * 8;

    for (int k0 = 0; k0 < IDIM; k0 += BK) {
        {
            float4 v0 = *(const float4*)(Arow + lr * IDIM + k0 + lkq);
            float4 v1 = *(const float4*)(Arow + lr * IDIM + k0 + lkq + 4);
            As[lkq + 0][lr] = v0.x; As[lkq + 1][lr] = v0.y;
            As[lkq + 2][lr] = v0.z; As[lkq + 3][lr] = v0.w;
            As[lkq + 4][lr] = v1.x; As[lkq + 5][lr] = v1.y;
            As[lkq + 6][lr] = v1.z; As[lkq + 7][lr] = v1.w;

            float4 w0 = *(const float4*)(Brow + lr * IDIM + k0 + lkq);
            float4 w1 = *(const float4*)(Brow + lr * IDIM + k0 + lkq + 4);
            Bs[lkq + 0][lr] = w0.x; Bs[lkq + 1][lr] = w0.y;
            Bs[lkq + 2][lr] = w0.z; Bs[lkq + 3][lr] = w0.w;
            Bs[lkq + 4][lr] = w1.x; Bs[lkq + 5][lr] = w1.y;
            Bs[lkq + 6][lr] = w1.z; Bs[lkq + 7][lr] = w1.w;
        }
        __syncthreads();

        #pragma unroll
        for (int kk = 0; kk < BK; kk++) {
            float4 av = *(const float4*)&As[kk][ty * 4];
            const uint64_t b01 = *(const uint64_t*)&Bs[kk][tx * 4];
            const uint64_t b23 = *(const uint64_t*)&Bs[kk][tx * 4 + 2];
            float a[4] = {av.x, av.y, av.z, av.w};
            #pragma unroll
            for (int i = 0; i < 4; i++) {
                uint64_t aa;
                asm("mov.b64 %0, {%1,%1};" : "=l"(aa) : "f"(a[i]));
                ffma2(acc01[i], aa, b01);
                ffma2(acc23[i], aa, b23);
            }
        }
        __syncthreads();
    }

    const int mb = mblk * BM + ty * 4;
    const int nb = nblk * BN + tx * 4;
    float bias[4];
    #pragma unroll
    for (int jj = 0; jj < 4; jj++)
        bias[jj] = bih[nb + jj] + bhh[nb + jj];

    #pragma unroll
    for (int i = 0; i < 4; i++) {
        uint32_t lo, hi, lo2, hi2;
        asm("mov.b64 {%0,%1}, %2;" : "=r"(lo), "=r"(hi) : "l"(acc01[i]));
        asm("mov.b64 {%0,%1}, %2;" : "=r"(lo2), "=r"(hi2) : "l"(acc23[i]));
        float4 v;
        v.x = __uint_as_float(lo)  + bias[0];
        v.y = __uint_as_float(hi)  + bias[1];
        v.z = __uint_as_float(lo2) + bias[2];
        v.w = __uint_as_float(hi2) + bias[3];
        *(float4*)&g_xg[(size_t)(mb + i) * G4 + nb] = v;
    }
}

// ---------------------------------------------------------------------------
// Kernel 2: dual-pair recurrence, 8-CTA clusters (R15 base), now with FOUR
// dedicated owner warps: warp 16 = (pair0,bb0), 17 = (pair0,bb1),
// 18 = (pair1,bb0), 19 = (pair1,bb1). Each owner thread reduces one batch
// (8 LDS), 4 activations, 1 c/h chain, 8 packed-b64 st.async — tail halved
// vs R15, hidden under the opposite pair's k-loop.
// Barriers: bar 1 (pair0) / bar 2 (pair1), 576 participants each.
// ---------------------------------------------------------------------------
__device__ __forceinline__ void mbar_wait(uint32_t addr, unsigned par) {
    asm volatile(
        "{\n\t"
        ".reg .pred P;\n\t"
        "WAIT_%=:\n\t"
        "mbarrier.try_wait.parity.acquire.cta.shared::cta.b64 P, [%0], %1, 0x989680;\n\t"
        "@P bra DONE_%=;\n\t"
        "bra WAIT_%=;\n\t"
        "DONE_%=:\n\t"
        "}"
        :: "r"(addr), "r"(par) : "memory");
}

#define TX_PER_BUF 2048   // 8 ranks x 64 floats x 4 B per pair-buffer

__global__ void __cluster_dims__(8, 1, 1) __launch_bounds__(640, 1)
lstm_rec_kernel(const float* __restrict__ Whh,
                const float* __restrict__ h0,
                const float* __restrict__ c0,
                float* __restrict__ out)
{
    __shared__ float h_s[2][2][2][HDIM];      // [pair][buf][bb][k]
    __shared__ float red_s[2][2][4][2][128];  // [pair][rd][kseg][bb][lr]
    __shared__ alignas(8) unsigned long long mbar[4];  // [pair*2 + buf]

    const int tid  = threadIdx.x;
    const int lane = tid & 31;
    const int w    = tid >> 5;

    unsigned rank;
    asm("mov.u32 %0, %%cluster_ctarank;" : "=r"(rank));
    const int b0 = (blockIdx.x >> 3) * 4;

    const uint32_t h_base  = (uint32_t)__cvta_generic_to_shared(&h_s[0][0][0][0]);
    const uint32_t mb_addr = (uint32_t)__cvta_generic_to_shared(&mbar[0]);

    // ---- shared init (all 640 threads) ----
    for (int i = tid; i < 4 * HDIM; i += 640) {
        const int bb = i >> 8, k = i & 255;
        h_s[bb >> 1][0][bb & 1][k] = h0[(size_t)(b0 + bb) * HDIM + k];
    }
    if (tid == 0) {
        #pragma unroll
        for (int q = 0; q < 4; q++) {
            asm volatile("mbarrier.init.shared.b64 [%0], %1;" :: "r"(mb_addr + q * 8), "r"(1) : "memory");
            asm volatile("mbarrier.arrive.expect_tx.shared.b64 _, [%0], %1;"
                         :: "r"(mb_addr + q * 8), "r"(TX_PER_BUF) : "memory");
        }
    }
    __syncthreads();
    asm volatile("barrier.cluster.arrive.aligned;" ::: "memory");
    asm volatile("barrier.cluster.wait.aligned;" ::: "memory");

    if (tid < 512) {
        // =================== COMPUTE WARPS ===================
        const int kseg = w >> 2;
        const int lr   = (w & 3) * 32 + lane;
        const int R    = ((lr >> 5) << 8) + (int)rank * 32 + (lr & 31);

        uint64_t wp[32];
        {
            const float* W = Whh + (size_t)R * HDIM + kseg * 64;
            #pragma unroll
            for (int i = 0; i < 16; i++) {
                float4 v = *(const float4*)(W + 4 * i);
                asm("mov.b64 %0, {%1,%2};" : "=l"(wp[2*i+0]) : "f"(v.x), "f"(v.y));
                asm("mov.b64 %0, {%1,%2};" : "=l"(wp[2*i+1]) : "f"(v.z), "f"(v.w));
            }
        }

        auto cphase = [&](int P, int rd, bool dowait, unsigned par) {
            const uint32_t mb_rd = mb_addr + (uint32_t)(P * 2 + rd) * 8;
            if (dowait) {
                mbar_wait(mb_rd, par);
                if (tid == 0)
                    asm volatile("mbarrier.arrive.expect_tx.shared.b64 _, [%0], %1;"
                                 :: "r"(mb_rd), "r"(TX_PER_BUF) : "memory");
            }
            const uint32_t a0 = h_base + (uint32_t)(((P * 2 + rd) * 2) * 256 + kseg * 64) * 4;
            const uint32_t a1 = a0 + 1024;
            uint64_t acc0 = 0ull, acc1 = 0ull;
            #pragma unroll
            for (int i = 0; i < 64; i += 4) {
                uint64_t u01, u23, v01, v23;
                asm volatile("ld.shared.v2.u64 {%0,%1}, [%2];"
                             : "=l"(u01), "=l"(u23) : "r"(a0 + i * 4));
                asm volatile("ld.shared.v2.u64 {%0,%1}, [%2];"
                             : "=l"(v01), "=l"(v23) : "r"(a1 + i * 4));
                ffma2(acc0, wp[i / 2 + 0], u01);
                ffma2(acc1, wp[i / 2 + 0], v01);
                ffma2(acc0, wp[i / 2 + 1], u23);
                ffma2(acc1, wp[i / 2 + 1], v23);
            }
            red_s[P][rd][kseg][0][lr] = hsum2(acc0);
            red_s[P][rd][kseg][1][lr] = hsum2(acc1);
            if (P == 0)
                asm volatile("bar.arrive 1, 576;" ::: "memory");
            else
                asm volatile("bar.arrive 2, 576;" ::: "memory");
        };

        unsigned parA[2] = {0, 0}, parB[2] = {0, 0};
        cphase(0, 0, false, 0);
        cphase(1, 0, false, 0);
        for (int t = SEQ - 2; t >= 2; t -= 2) {
            cphase(0, 1, true, parA[1]);
            cphase(1, 1, true, parB[1]);  parA[1] ^= 1; parB[1] ^= 1;
            cphase(0, 0, true, parA[0]);
            cphase(1, 0, true, parB[0]);  parA[0] ^= 1; parB[0] ^= 1;
        }
        cphase(0, 1, true, parA[1]);
        cphase(1, 1, true, parB[1]);
    } else {
        // =================== OWNER WARPS (one per pair x batch) ===================
        const int ow = w - 16;              // 0..3
        const int P  = ow >> 1;             // pair
        const int bb = ow & 1;              // batch within pair
        const int j  = lane;                // hidden unit 0..31
        const int kglob = (int)rank * 32 + j;
        const int bcur  = b0 + 2 * P + bb;
        const uint32_t mb_delta = mb_addr - h_base;

        uint32_t ph[8];
        #pragma unroll
        for (int r = 0; r < 8; r++)
            asm("mapa.shared::cluster.u32 %0, %1, %2;" : "=r"(ph[r]) : "r"(h_base), "r"(r));

        float c_reg = c0[(size_t)bcur * HDIM + kglob];
        float h_keep = 0.f;

        for (int t = SEQ - 1; t >= 0; t--) {
            const int rd = (t + 1) & 1;

            // xg prefetch (covered by the bar wait below)
            const float* xp = g_xg + ((size_t)t * BATCH + bcur) * G4 + kglob;
            const float a0v = __ldg(xp);
            const float a1v = __ldg(xp + 256);
            const float a2v = __ldg(xp + 512);
            const float a3v = __ldg(xp + 768);

            if (P == 0)
                asm volatile("bar.sync 1, 576;" ::: "memory");
            else
                asm volatile("bar.sync 2, 576;" ::: "memory");

            float s0 = a0v, s1 = a1v, s2 = a2v, s3 = a3v;
            #pragma unroll
            for (int ks = 0; ks < 4; ks++) {
                const float* rp = &red_s[P][rd][ks][bb][0];
                s0 += rp[ 0 + j];
                s1 += rp[32 + j];
                s2 += rp[64 + j];
                s3 += rp[96 + j];
            }

            const float ig = __fdividef(1.f, 1.f + __expf(-s0));
            const float fg = __fdividef(1.f, 1.f + __expf(-s1));
            const float gt = 1.f - 2.f * __fdividef(1.f, 1.f + __expf(2.f * s2));
            const float og = __fdividef(1.f, 1.f + __expf(-s3));

            c_reg = fg * c_reg + ig * gt;
            const float h = og * (1.f - 2.f * __fdividef(1.f, 1.f + __expf(2.f * c_reg)));
            h_keep = h;

            if (t > 0) {
                const int wr = rd ^ 1;
                const float hn = __shfl_down_sync(0xffffffffu, h, 1);
                if ((lane & 1) == 0) {
                    uint64_t hp;
                    asm("mov.b64 %0, {%1,%2};" : "=l"(hp) : "f"(h), "f"(hn));
                    const uint32_t ho = (uint32_t)((((P * 2 + wr) * 2 + bb) * 256 + kglob) * 4);
                    const uint32_t mo = mb_delta + (uint32_t)(P * 2 + wr) * 8;
                    #pragma unroll
                    for (int r = 0; r < 8; r++) {
                        asm volatile(
                            "st.async.shared::cluster.mbarrier::complete_tx::bytes.b64 [%0], %1, [%2];"
                            :: "r"(ph[r] + ho), "l"(hp), "r"(ph[r] + mo) : "memory");
                    }
                }
            }

            out[((size_t)t * BATCH + bcur) * HDIM + kglob] = h;
        }

        float* hT = out + (size_t)SEQ * BATCH * HDIM;
        float* cT = hT + (size_t)BATCH * HDIM;
        hT[(size_t)bcur * HDIM + kglob] = h_keep;
        cT[(size_t)bcur * HDIM + kglob] = c_reg;
    }
}

// ---------------------------------------------------------------------------
extern "C" void kernel_launch(void* const* d_in, const int* in_sizes, int n_in,
                              void* d_out, int out_size)
{
    (void)in_sizes; (void)n_in; (void)out_size;
    const float* x   = (const float*)d_in[0];
    const float* h0  = (const float*)d_in[1];
    const float* c0  = (const float*)d_in[2];
    const float* Wih = (const float*)d_in[3];
    const float* Whh = (const float*)d_in[4];
    const float* bih = (const float*)d_in[5];
    const float* bhh = (const float*)d_in[6];
    float* out = (float*)d_out;

    dim3 gridP(65536 / BM, G4 / BN);   // (1024, 16)
    xproj_kernel<<<gridP, 256>>>(x, Wih, bih, bhh);

    // 8 clusters x 8 CTAs, 4 batches per cluster, 4 dedicated owner warps
    lstm_rec_kernel<<<64, 640>>>(Whh, h0, c0, out);
}